// round 13
// baseline (speedup 1.0000x reference)
#include <cuda_runtime.h>
#include <cuda_fp16.h>
#include <math.h>
#include <stdint.h>

// out = sigmoid(decay)*h + x @ W^T + b ; x:[M,K] W:[N,K] fp32
#define M_DIM 16384
#define N_DIM 2048
#define K_DIM 2048

#define BM 128
#define BN 128
#define BK 64
#define STAGES 3
#define NTHREADS 512
#define KTILES (K_DIM / BK)        // 32

#define A_STAGE_BYTES 16384        // 128 rows * 128B
#define B_STAGE_BYTES 16384        // 128 rows * 128B
#define STAGE_BYTES (A_STAGE_BYTES + B_STAGE_BYTES)   // 32768
#define SMEM_TOTAL (STAGES * STAGE_BYTES)             // 98304 -> 2 CTAs/SM

// ---- scratch: fp16 copies ----
__device__ __align__(1024) unsigned char g_xh[(size_t)M_DIM * K_DIM * 2];
__device__ __align__(1024) unsigned char g_wh[(size_t)N_DIM * K_DIM * 2];
__device__ float g_alpha[N_DIM];

__device__ __forceinline__ uint32_t smem_u32(const void* p) {
    uint32_t a;
    asm("{ .reg .u64 t; cvta.to.shared.u64 t, %1; cvt.u32.u64 %0, t; }" : "=r"(a) : "l"(p));
    return a;
}

#define CP16(dst, src) \
    asm volatile("cp.async.cg.shared.global [%0], [%1], 16;" :: "r"(dst), "l"(src) : "memory")
#define CP_COMMIT() asm volatile("cp.async.commit_group;" ::: "memory")
#define CP_WAIT1()  asm volatile("cp.async.wait_group 1;" ::: "memory")

#define LDSM_X4(r0, r1, r2, r3, addr) \
    asm volatile("ldmatrix.sync.aligned.m8n8.x4.shared.b16 {%0,%1,%2,%3}, [%4];" \
        : "=r"(r0), "=r"(r1), "=r"(r2), "=r"(r3) : "r"(addr))

#define MMA_F16(d, a, b0, b1) \
    asm volatile("mma.sync.aligned.m16n8k16.row.col.f32.f16.f16.f32 " \
        "{%0,%1,%2,%3}, {%4,%5,%6,%7}, {%8,%9}, {%0,%1,%2,%3};" \
        : "+f"((d)[0]), "+f"((d)[1]), "+f"((d)[2]), "+f"((d)[3]) \
        : "r"((a)[0]), "r"((a)[1]), "r"((a)[2]), "r"((a)[3]), "r"(b0), "r"(b1))

// ---- convert kernels ----
__device__ __forceinline__ void cvt8(const float* src, unsigned char* dst, size_t off8) {
    float4 v0 = *(const float4*)(src + off8);
    float4 v1 = *(const float4*)(src + off8 + 4);
    float v[8] = {v0.x, v0.y, v0.z, v0.w, v1.x, v1.y, v1.z, v1.w};
    uint32_t p[4];
#pragma unroll
    for (int i = 0; i < 4; ++i) {
        __half h0 = __float2half_rn(v[2 * i]);
        __half h1 = __float2half_rn(v[2 * i + 1]);
        p[i] = (uint32_t)__half_as_ushort(h0) | ((uint32_t)__half_as_ushort(h1) << 16);
    }
    *(uint4*)(dst + off8 * 2) = make_uint4(p[0], p[1], p[2], p[3]);
}

__global__ void cvt_x_kernel(const float* __restrict__ x) {
    size_t idx = (size_t)blockIdx.x * 256 + threadIdx.x;
    cvt8(x, g_xh, idx << 3);
}
__global__ void cvt_w_kernel(const float* __restrict__ W) {
    size_t idx = (size_t)blockIdx.x * 256 + threadIdx.x;
    cvt8(W, g_wh, idx << 3);
}
__global__ void cvt_alpha_kernel(const float* __restrict__ decay) {
    int i = blockIdx.x * 256 + threadIdx.x;
    if (i < N_DIM) g_alpha[i] = 1.0f / (1.0f + expf(-decay[i]));
}

// ---- GEMM stage loader: 512 threads; A 1024x16B + B 1024x16B -> 2+2 per thread ----
__device__ __forceinline__ void issue_stage_loads(uint32_t sb, int stg, int kt,
                                                  int mBase, int nBase, int tid) {
    const uint32_t sA = sb + stg * STAGE_BYTES;
    const uint32_t sB = sA + A_STAGE_BYTES;
    const int row = tid >> 2;                    // 0..127
    const int c0  = (tid & 3) << 1;              // 0,2,4,6
    const uint32_t rx = (uint32_t)((row & 7) << 4);
    const unsigned char* srcA = g_xh +
        (((size_t)(mBase + row) * K_DIM + (size_t)kt * BK) << 1) + c0 * 16;
    const unsigned char* srcB = g_wh +
        (((size_t)(nBase + row) * K_DIM + (size_t)kt * BK) << 1) + c0 * 16;
    const uint32_t dA = sA + (uint32_t)row * 128;
    const uint32_t dB = sB + (uint32_t)row * 128;
#pragma unroll
    for (int c = 0; c < 2; ++c) {
        const uint32_t co = ((uint32_t)((c0 + c) * 16)) ^ rx;
        CP16(dA + co, srcA + c * 16);
        CP16(dB + co, srcB + c * 16);
    }
}

__global__ void __launch_bounds__(NTHREADS, 2)
lrnn_gemm_hmma(const float* __restrict__ h,
               const float* __restrict__ bias,
               float* __restrict__ out,
               int write_twice)
{
    extern __shared__ char smem[];
    const uint32_t sb = smem_u32(smem);
    const int tid  = threadIdx.x;
    const int lane = tid & 31;
    const int wid  = tid >> 5;        // 0..15
    const int wm = wid >> 2;          // 0..3  (32-row strip)
    const int wn = wid & 3;           // 0..3  (32-col strip)
    const int nBase = blockIdx.x * BN;
    const int mBase = blockIdx.y * BM;

    float d[2][4][4];
#pragma unroll
    for (int i = 0; i < 2; ++i)
#pragma unroll
        for (int j = 0; j < 4; ++j)
#pragma unroll
            for (int q = 0; q < 4; ++q) d[i][j][q] = 0.0f;

    issue_stage_loads(sb, 0, 0, mBase, nBase, tid);
    CP_COMMIT();
    issue_stage_loads(sb, 1, 1, mBase, nBase, tid);
    CP_COMMIT();

    const uint32_t rx = (uint32_t)((lane & 7) << 4);
    const uint32_t kl = (uint32_t)(lane & 16);          // k8-half select (16B)
    const uint32_t rowA = (uint32_t)(wm * 32 + (lane & 15)) * 128;
    const uint32_t rowB = (uint32_t)(wn * 32 + (lane & 15)) * 128 + A_STAGE_BYTES;

    // per-warp ks phase stagger: warp w starts at ks = w&3 (all ks resident in smem)
    uint32_t koff[4];
#pragma unroll
    for (int q = 0; q < 4; ++q) {
        const int ks = (q + wid) & 3;
        koff[q] = (((uint32_t)(ks * 32)) + kl) ^ rx;
    }

    uint32_t aF[2][2][4];   // A frags: double-buffered across ks
    uint32_t bF[4][2];      // B frags: JIT single buffer

#define LOAD_A(buf, sg, q)                                                          \
    do {                                                                            \
        _Pragma("unroll")                                                           \
        for (int i = 0; i < 2; ++i)                                                 \
            LDSM_X4(aF[buf][i][0], aF[buf][i][1], aF[buf][i][2], aF[buf][i][3],     \
                    (sg) + rowA + (uint32_t)(i * 16) * 128 + koff[q]);              \
    } while (0)

#define LOAD_B(sg, q)                                                               \
    do {                                                                            \
        _Pragma("unroll")                                                           \
        for (int jp = 0; jp < 2; ++jp) {                                            \
            uint32_t r0, r1, r2, r3;                                                \
            LDSM_X4(r0, r1, r2, r3,                                                 \
                    (sg) + rowB + (uint32_t)(jp * 16) * 128 + koff[q]);             \
            bF[jp * 2][0] = r0; bF[jp * 2 + 1][0] = r1;                             \
            bF[jp * 2][1] = r2; bF[jp * 2 + 1][1] = r3;                             \
        }                                                                           \
    } while (0)

#define MMA_KS(buf)                                                                 \
    do {                                                                            \
        _Pragma("unroll")                                                           \
        for (int i = 0; i < 2; ++i)                                                 \
            _Pragma("unroll")                                                       \
            for (int j = 0; j < 4; ++j)                                             \
                MMA_F16(d[i][j], aF[buf][i], bF[j][0], bF[j][1]);                   \
    } while (0)

    for (int t = 0; t < KTILES; ++t) {
        CP_WAIT1();            // tile t resident; tile t+1 in flight
        __syncthreads();

        if (t + 2 < KTILES)
            issue_stage_loads(sb, (t + 2) % STAGES, t + 2, mBase, nBase, tid);
        CP_COMMIT();

        const uint32_t sg = sb + (uint32_t)(t % STAGES) * STAGE_BYTES;

        // A one step ahead; warps enter at staggered ks phases
        LOAD_A(0, sg, 0);
#pragma unroll
        for (int q = 0; q < 4; ++q) {
            const int cur = q & 1;
            LOAD_B(sg, q);
            if (q < 3) LOAD_A(cur ^ 1, sg, q + 1);
            MMA_KS(cur);
        }
    }

    // ---- fused epilogue ----
    const size_t dual = (size_t)M_DIM * N_DIM;
#pragma unroll
    for (int j = 0; j < 4; ++j) {
        const int c = nBase + wn * 32 + j * 8 + (lane & 3) * 2;
        const float al0 = g_alpha[c],  al1 = g_alpha[c + 1];
        const float bb0 = bias[c],     bb1 = bias[c + 1];
#pragma unroll
        for (int i = 0; i < 2; ++i) {
            const int r0 = mBase + wm * 32 + i * 16 + (lane >> 2);
            const size_t o0 = (size_t)r0 * N_DIM + c;
            const size_t o1 = o0 + 8 * N_DIM;
            float2 h0 = *(const float2*)(h + o0);
            float2 h1 = *(const float2*)(h + o1);
            float2 v0, v1;
            v0.x = fmaf(al0, h0.x, d[i][j][0] + bb0);
            v0.y = fmaf(al1, h0.y, d[i][j][1] + bb1);
            v1.x = fmaf(al0, h1.x, d[i][j][2] + bb0);
            v1.y = fmaf(al1, h1.y, d[i][j][3] + bb1);
            *(float2*)(out + o0) = v0;
            *(float2*)(out + o1) = v1;
            if (write_twice) {
                *(float2*)(out + dual + o0) = v0;
                *(float2*)(out + dual + o1) = v1;
            }
        }
    }
}

extern "C" void kernel_launch(void* const* d_in, const int* in_sizes, int n_in,
                              void* d_out, int out_size)
{
    const float* x     = (const float*)d_in[0];
    const float* h     = (const float*)d_in[1];
    const float* W     = (const float*)d_in[2];
    const float* b     = (const float*)d_in[3];
    const float* decay = (const float*)d_in[4];
    float* out = (float*)d_out;

    const long long total = (long long)M_DIM * N_DIM;
    const int write_twice = ((long long)out_size >= 2 * total) ? 1 : 0;

    cudaFuncSetAttribute(lrnn_gemm_hmma, cudaFuncAttributeMaxDynamicSharedMemorySize, SMEM_TOTAL);

    cvt_x_kernel<<<(int)(((size_t)M_DIM * K_DIM / 8) / 256), 256>>>(x);
    cvt_w_kernel<<<(int)(((size_t)N_DIM * K_DIM / 8) / 256), 256>>>(W);
    cvt_alpha_kernel<<<(N_DIM + 255) / 256, 256>>>(decay);

    dim3 grid(N_DIM / BN, M_DIM / BM);   // (16, 128) = 2048 CTAs
    lrnn_gemm_hmma<<<grid, NTHREADS, SMEM_TOTAL>>>(h, b, out, write_twice);
}

// round 15
// speedup vs baseline: 1.0570x; 1.0570x over previous
#include <cuda_runtime.h>
#include <cuda_fp16.h>
#include <math.h>
#include <stdint.h>

// out = sigmoid(decay)*h + x @ W^T + b ; x:[M,K] W:[N,K] fp32
#define M_DIM 16384
#define N_DIM 2048
#define K_DIM 2048

#define BM 256
#define BN 128
#define BK 64
#define NSTAGE 4
#define NTHREADS 512
#define KTILES (K_DIM / BK)        // 32

#define A_STAGE_BYTES 32768        // 256 rows * 128B
#define B_STAGE_BYTES 16384        // 128 rows * 128B
#define STAGE_BYTES (A_STAGE_BYTES + B_STAGE_BYTES)   // 49152
#define SM_STAGE0 1024
#define SMEM_TOTAL (SM_STAGE0 + NSTAGE * STAGE_BYTES) // 197632 -> 1 CTA/SM

// ---- scratch: fp16 copies ----
__device__ __align__(1024) unsigned char g_xh[(size_t)M_DIM * K_DIM * 2];
__device__ __align__(1024) unsigned char g_wh[(size_t)N_DIM * K_DIM * 2];
__device__ float g_alpha[N_DIM];

__device__ __forceinline__ uint32_t smem_u32(const void* p) {
    uint32_t a;
    asm("{ .reg .u64 t; cvta.to.shared.u64 t, %1; cvt.u32.u64 %0, t; }" : "=r"(a) : "l"(p));
    return a;
}

#define CP16(dst, src) \
    asm volatile("cp.async.cg.shared.global [%0], [%1], 16;" :: "r"(dst), "l"(src) : "memory")

#define MBAR_INIT(mbar, cnt) \
    asm volatile("mbarrier.init.shared.b64 [%0], %1;" :: "r"(mbar), "r"(cnt) : "memory")
#define MBAR_ARRIVE(mbar) \
    asm volatile("mbarrier.arrive.shared.b64 _, [%0];" :: "r"(mbar) : "memory")
// Async-group arrive: inc form (libcu++ pattern) — MUST be paired with an
// explicit mbarrier.arrive from the same thread; the inc form adds 1 pending
// before the async completion removes it (net zero without the explicit arrive).
#define CPASYNC_MBAR_ARRIVE(mbar) \
    asm volatile("cp.async.mbarrier.arrive.shared.b64 [%0];" :: "r"(mbar) : "memory")
#define MBAR_WAIT(mbar, parity) do { \
    uint32_t _m = (mbar), _p = (parity), _d; \
    asm volatile("{\n\t.reg .pred p;\n\t" \
        "mbarrier.try_wait.parity.shared.b64 p, [%1], %2;\n\t" \
        "selp.b32 %0, 1, 0, p;\n\t}" : "=r"(_d) : "r"(_m), "r"(_p) : "memory"); \
    if (!_d) { \
        asm volatile("{\n\t.reg .pred P1;\n\t" \
            "W_%=:\n\t" \
            "mbarrier.try_wait.parity.shared.b64 P1, [%0], %1;\n\t" \
            "@P1 bra.uni D_%=;\n\t" \
            "bra.uni W_%=;\n\t" \
            "D_%=:\n\t}" :: "r"(_m), "r"(_p) : "memory"); \
    } \
} while (0)

#define LDSM_X4(r0, r1, r2, r3, addr) \
    asm volatile("ldmatrix.sync.aligned.m8n8.x4.shared.b16 {%0,%1,%2,%3}, [%4];" \
        : "=r"(r0), "=r"(r1), "=r"(r2), "=r"(r3) : "r"(addr))

#define MMA_F16(d, a, b0, b1) \
    asm volatile("mma.sync.aligned.m16n8k16.row.col.f32.f16.f16.f32 " \
        "{%0,%1,%2,%3}, {%4,%5,%6,%7}, {%8,%9}, {%0,%1,%2,%3};" \
        : "+f"((d)[0]), "+f"((d)[1]), "+f"((d)[2]), "+f"((d)[3]) \
        : "r"((a)[0]), "r"((a)[1]), "r"((a)[2]), "r"((a)[3]), "r"(b0), "r"(b1))

// ---- convert kernels ----
__device__ __forceinline__ void cvt8(const float* src, unsigned char* dst, size_t off8) {
    float4 v0 = *(const float4*)(src + off8);
    float4 v1 = *(const float4*)(src + off8 + 4);
    float v[8] = {v0.x, v0.y, v0.z, v0.w, v1.x, v1.y, v1.z, v1.w};
    uint32_t p[4];
#pragma unroll
    for (int i = 0; i < 4; ++i) {
        __half h0 = __float2half_rn(v[2 * i]);
        __half h1 = __float2half_rn(v[2 * i + 1]);
        p[i] = (uint32_t)__half_as_ushort(h0) | ((uint32_t)__half_as_ushort(h1) << 16);
    }
    *(uint4*)(dst + off8 * 2) = make_uint4(p[0], p[1], p[2], p[3]);
}

__global__ void cvt_x_kernel(const float* __restrict__ x) {
    size_t idx = (size_t)blockIdx.x * 256 + threadIdx.x;
    cvt8(x, g_xh, idx << 3);
}
__global__ void cvt_w_kernel(const float* __restrict__ W) {
    size_t idx = (size_t)blockIdx.x * 256 + threadIdx.x;
    cvt8(W, g_wh, idx << 3);
}
__global__ void cvt_alpha_kernel(const float* __restrict__ decay) {
    int i = blockIdx.x * 256 + threadIdx.x;
    if (i < N_DIM) g_alpha[i] = 1.0f / (1.0f + expf(-decay[i]));
}

// ---- stage loader: 512 threads; A 2048x16B (4/thr) + B 1024x16B (2/thr) ----
__device__ __forceinline__ void issue_stage_loads(uint32_t sb, int stg, int kt,
                                                  int mBase, int nBase, int tid) {
    const uint32_t sA = sb + SM_STAGE0 + stg * STAGE_BYTES;
    const uint32_t sB = sA + A_STAGE_BYTES;
    // A
    {
        const int row = tid >> 1;                    // 0..255
        const int c0  = (tid & 1) << 2;              // 0 or 4
        const uint32_t rx = (uint32_t)((row & 7) << 4);
        const unsigned char* srcA = g_xh +
            (((size_t)(mBase + row) * K_DIM + (size_t)kt * BK) << 1) + c0 * 16;
        const uint32_t dA = sA + (uint32_t)row * 128;
#pragma unroll
        for (int c = 0; c < 4; ++c)
            CP16(dA + ((((uint32_t)((c0 + c) * 16))) ^ rx), srcA + c * 16);
    }
    // B
    {
        const int row = tid >> 2;                    // 0..127
        const int c0  = (tid & 3) << 1;              // 0,2,4,6
        const uint32_t rx = (uint32_t)((row & 7) << 4);
        const unsigned char* srcB = g_wh +
            (((size_t)(nBase + row) * K_DIM + (size_t)kt * BK) << 1) + c0 * 16;
        const uint32_t dB = sB + (uint32_t)row * 128;
#pragma unroll
        for (int c = 0; c < 2; ++c)
            CP16(dB + ((((uint32_t)((c0 + c) * 16))) ^ rx), srcB + c * 16);
    }
}

__global__ void __launch_bounds__(NTHREADS, 1)
lrnn_gemm_hmma(const float* __restrict__ h,
               const float* __restrict__ bias,
               float* __restrict__ out,
               int write_twice)
{
    extern __shared__ char smem[];
    const uint32_t sb = smem_u32(smem);
    const int tid  = threadIdx.x;
    const int lane = tid & 31;
    const int wid  = tid >> 5;        // 0..15
    const int wm = wid >> 2;          // 0..3  (64-row strip)
    const int wn = wid & 3;           // 0..3  (32-col strip)
    const int nBase = blockIdx.x * BN;
    const int mBase = blockIdx.y * BM;

    // mbarriers: full[s] at sb+16*s, empty[s] at sb+16*s+8
    if (tid == 0) {
#pragma unroll
        for (int s = 0; s < NSTAGE; ++s) {
            MBAR_INIT(sb + 16 * s, NTHREADS);   // full: 512 thread arrivals (+async inc/dec)
            MBAR_INIT(sb + 16 * s + 8, 16);     // empty: 16 warp arrivals
        }
    }
    __syncthreads();

    float d[4][4][4];
#pragma unroll
    for (int i = 0; i < 4; ++i)
#pragma unroll
        for (int j = 0; j < 4; ++j)
#pragma unroll
            for (int q = 0; q < 4; ++q) d[i][j][q] = 0.0f;

    // prologue: produce tiles 0 and 1 (empty-wait passes: fresh barriers, parity 1)
#pragma unroll
    for (int pt = 0; pt < 2; ++pt) {
        MBAR_WAIT(sb + 16 * pt + 8, 1u);
        issue_stage_loads(sb, pt, pt, mBase, nBase, tid);
        CPASYNC_MBAR_ARRIVE(sb + 16 * pt);   // track this thread's cp.asyncs (inc form)
        MBAR_ARRIVE(sb + 16 * pt);           // explicit thread arrive (consumes init count)
    }

    const uint32_t rx = (uint32_t)((lane & 7) << 4);
    const uint32_t kl = (uint32_t)(lane & 16);          // k8-half select (16B)
    const uint32_t rowA = (uint32_t)(wm * 64 + (lane & 15)) * 128 + SM_STAGE0;
    const uint32_t rowB = (uint32_t)(wn * 32 + (lane & 15)) * 128 + SM_STAGE0 + A_STAGE_BYTES;

    for (int t = 0; t < KTILES; ++t) {
        // produce tile t+2 (backpressure: all warps done reading tile t-2)
        if (t + 2 < KTILES) {
            const int pt = t + 2;
            MBAR_WAIT(sb + 16 * (pt & 3) + 8, 1u ^ ((uint32_t)(pt >> 2) & 1u));
            issue_stage_loads(sb, pt & 3, pt, mBase, nBase, tid);
            CPASYNC_MBAR_ARRIVE(sb + 16 * (pt & 3));
            MBAR_ARRIVE(sb + 16 * (pt & 3));
        }

        // consume tile t
        MBAR_WAIT(sb + 16 * (t & 3), (uint32_t)(t >> 2) & 1u);
        const uint32_t sg = (uint32_t)(t & 3) * STAGE_BYTES;

#pragma unroll
        for (int ks = 0; ks < 4; ++ks) {
            const uint32_t koff = (((uint32_t)(ks * 32)) + kl) ^ rx;
            uint32_t aF[4][4];
#pragma unroll
            for (int i = 0; i < 4; ++i) {
                const uint32_t ra = sb + sg + rowA + (uint32_t)(i * 16) * 128 + koff;
                LDSM_X4(aF[i][0], aF[i][1], aF[i][2], aF[i][3], ra);
            }
            uint32_t bF[4][2];
#pragma unroll
            for (int jp = 0; jp < 2; ++jp) {
                uint32_t r0, r1, r2, r3;
                LDSM_X4(r0, r1, r2, r3, sb + sg + rowB + (uint32_t)(jp * 16) * 128 + koff);
                bF[jp * 2][0] = r0; bF[jp * 2 + 1][0] = r1;
                bF[jp * 2][1] = r2; bF[jp * 2 + 1][1] = r3;
            }
#pragma unroll
            for (int i = 0; i < 4; ++i)
#pragma unroll
                for (int j = 0; j < 4; ++j)
                    MMA_F16(d[i][j], aF[i], bF[j][0], bF[j][1]);
        }

        // reads of stage (t&3) complete (MMAs consumed frags) -> release buffer
        if (lane == 0) MBAR_ARRIVE(sb + 16 * (t & 3) + 8);
    }

    // ---- fused epilogue ----
    const size_t dual = (size_t)M_DIM * N_DIM;
#pragma unroll
    for (int j = 0; j < 4; ++j) {
        const int c = nBase + wn * 32 + j * 8 + (lane & 3) * 2;
        const float al0 = g_alpha[c],  al1 = g_alpha[c + 1];
        const float bb0 = bias[c],     bb1 = bias[c + 1];
#pragma unroll
        for (int i = 0; i < 4; ++i) {
            const int r0 = mBase + wm * 64 + i * 16 + (lane >> 2);
            const size_t o0 = (size_t)r0 * N_DIM + c;
            const size_t o1 = o0 + 8 * N_DIM;
            float2 h0 = *(const float2*)(h + o0);
            float2 h1 = *(const float2*)(h + o1);
            float2 v0, v1;
            v0.x = fmaf(al0, h0.x, d[i][j][0] + bb0);
            v0.y = fmaf(al1, h0.y, d[i][j][1] + bb1);
            v1.x = fmaf(al0, h1.x, d[i][j][2] + bb0);
            v1.y = fmaf(al1, h1.y, d[i][j][3] + bb1);
            *(float2*)(out + o0) = v0;
            *(float2*)(out + o1) = v1;
            if (write_twice) {
                *(float2*)(out + dual + o0) = v0;
                *(float2*)(out + dual + o1) = v1;
            }
        }
    }
}

extern "C" void kernel_launch(void* const* d_in, const int* in_sizes, int n_in,
                              void* d_out, int out_size)
{
    const float* x     = (const float*)d_in[0];
    const float* h     = (const float*)d_in[1];
    const float* W     = (const float*)d_in[2];
    const float* b     = (const float*)d_in[3];
    const float* decay = (const float*)d_in[4];
    float* out = (float*)d_out;

    const long long total = (long long)M_DIM * N_DIM;
    const int write_twice = ((long long)out_size >= 2 * total) ? 1 : 0;

    cudaFuncSetAttribute(lrnn_gemm_hmma, cudaFuncAttributeMaxDynamicSharedMemorySize, SMEM_TOTAL);

    cvt_x_kernel<<<(int)(((size_t)M_DIM * K_DIM / 8) / 256), 256>>>(x);
    cvt_w_kernel<<<(int)(((size_t)N_DIM * K_DIM / 8) / 256), 256>>>(W);
    cvt_alpha_kernel<<<(N_DIM + 255) / 256, 256>>>(decay);

    dim3 grid(N_DIM / BN, M_DIM / BM);   // (16, 64) = 1024 CTAs
    lrnn_gemm_hmma<<<grid, NTHREADS, SMEM_TOTAL>>>(h, b, out, write_twice);
}